// round 2
// baseline (speedup 1.0000x reference)
#include <cuda_runtime.h>

#define NMAX 100000
#define EMAX 800000

// Scratch (static __device__ arrays per allocation rules)
__device__ float g_h[NMAX * 64];     // per-layer transformed features
__device__ float g_agg[NMAX * 64];   // layer-1 output (post relu)
__device__ float g_Wf[384 * 64];     // Wm @ W1 fused weight
__device__ float g_bf[64];           // bm @ W1 fused bias
__device__ float g_dinv[NMAX];       // deg accumulator, then rsqrt(deg)
__device__ int   g_cnt[NMAX];        // in-degree (edge count) per node
__device__ int   g_rowptr[NMAX];     // exclusive prefix of g_cnt
__device__ int   g_pos[NMAX];        // fill cursors
__device__ int   g_ssrc[EMAX];       // CSR: source node per (dst-sorted) edge
__device__ float g_snorm[EMAX];      // CSR: norm per (dst-sorted) edge
__device__ int   g_bsum[128];
__device__ int   g_bscan[128];

// ---------------- preprocessing ----------------

__global__ void k_init(int n) {
    int i = blockIdx.x * blockDim.x + threadIdx.x;
    if (i < n) { g_dinv[i] = 1.0f; g_cnt[i] = 0; }  // self-loop weight 1 pre-seeded
}

__global__ void k_deg(const int* __restrict__ src, const int* __restrict__ dst,
                      const float* __restrict__ w, int e) {
    int i = blockIdx.x * blockDim.x + threadIdx.x;
    if (i < e) {
        int d = dst[i];
        atomicAdd(&g_dinv[d], w[i]);
        atomicAdd(&g_cnt[d], 1);
    }
}

__global__ void k_dinv(int n) {
    int i = blockIdx.x * blockDim.x + threadIdx.x;
    if (i < n) g_dinv[i] = rsqrtf(g_dinv[i]);   // deg >= 1 always (self loop)
}

__global__ void k_scan1(int n) {   // 1024 threads/block
    __shared__ int sh[1024];
    int t = threadIdx.x;
    int i = blockIdx.x * 1024 + t;
    int v = (i < n) ? g_cnt[i] : 0;
    sh[t] = v; __syncthreads();
    #pragma unroll
    for (int off = 1; off < 1024; off <<= 1) {
        int x = (t >= off) ? sh[t - off] : 0;
        __syncthreads();
        sh[t] += x;
        __syncthreads();
    }
    if (i < n) g_rowptr[i] = sh[t] - v;          // block-local exclusive
    if (t == 1023) g_bsum[blockIdx.x] = sh[1023];
}

__global__ void k_scan2(int nb) {  // single block of 128
    __shared__ int sh[128];
    int t = threadIdx.x;
    int v = (t < nb) ? g_bsum[t] : 0;
    sh[t] = v; __syncthreads();
    #pragma unroll
    for (int off = 1; off < 128; off <<= 1) {
        int x = (t >= off) ? sh[t - off] : 0;
        __syncthreads();
        sh[t] += x;
        __syncthreads();
    }
    if (t < nb) g_bscan[t] = sh[t] - v;
}

__global__ void k_scan3(int n) {
    int i = blockIdx.x * blockDim.x + threadIdx.x;
    if (i < n) {
        int r = g_rowptr[i] + g_bscan[i >> 10];
        g_rowptr[i] = r;
        g_pos[i] = r;
    }
}

__global__ void k_fill(const int* __restrict__ src, const int* __restrict__ dst,
                       const float* __restrict__ w, int e) {
    int i = blockIdx.x * blockDim.x + threadIdx.x;
    if (i < e) {
        int d = dst[i], s = src[i];
        int p = atomicAdd(&g_pos[d], 1);
        g_ssrc[p] = s;
        g_snorm[p] = g_dinv[s] * w[i] * g_dinv[d];
    }
}

// ---------------- weight fusion: Wf = Wm @ W1, bf = bm @ W1 ----------------

__global__ void k_fuseW(const float* __restrict__ Wm, const float* __restrict__ W1,
                        float* __restrict__ Wf) {
    int i = blockIdx.x * blockDim.x + threadIdx.x;   // 0..384*64
    if (i >= 384 * 64) return;
    int r = i >> 6, c = i & 63;
    float s = 0.f;
    #pragma unroll 8
    for (int k = 0; k < 64; k++) s += Wm[r * 64 + k] * W1[k * 64 + c];
    Wf[i] = s;
}

__global__ void k_fuseb(const float* __restrict__ bm, const float* __restrict__ W1,
                        float* __restrict__ bf) {
    int c = threadIdx.x;
    float s = 0.f;
    #pragma unroll 8
    for (int k = 0; k < 64; k++) s += bm[k] * W1[k * 64 + c];
    bf[c] = s;
}

// ---------------- FFMA2 GEMM: C[n,64] = A[n,K] @ W[K,64] (+bias) ----------
// BM=128, BN=64, BK=16, 128 threads, per-thread tile 8 rows x 8 cols,
// accumulators packed over column pairs via fma.rn.f32x2 (2x fp32 rate).

__device__ __forceinline__ void ffma2(unsigned long long& d,
                                      unsigned long long a,
                                      unsigned long long b) {
    asm volatile("fma.rn.f32x2 %0, %1, %2, %0;" : "+l"(d) : "l"(a), "l"(b));
}

__device__ __forceinline__ float2 unpack2(unsigned long long v) {
    float2 r;
    asm("mov.b64 {%0, %1}, %2;" : "=f"(r.x), "=f"(r.y) : "l"(v));
    return r;
}

__global__ __launch_bounds__(128)
void k_gemm(const float* __restrict__ A, const float* __restrict__ W,
            const float* __restrict__ bias, float* __restrict__ C,
            int n, int K) {
    __shared__ float As[16][256];   // A duplicated: As[k][2r] = As[k][2r+1] = A[row r][k]
    __shared__ float Bs[16][64];
    int t = threadIdx.x;
    int rowBase = blockIdx.x * 128;
    int ty = t >> 3;          // 0..15 -> 8 rows each
    int tx = t & 7;           // 0..7  -> 8 cols each

    unsigned long long acc[8][4];
    #pragma unroll
    for (int i = 0; i < 8; i++)
        #pragma unroll
        for (int q = 0; q < 4; q++) acc[i][q] = 0ull;

    for (int k0 = 0; k0 < K; k0 += 16) {
        // load A tile (128 rows x 16 k), duplicated-transposed into As[k][2r(,+1)]
        #pragma unroll
        for (int l = 0; l < 4; l++) {
            int lin = t + l * 128;          // 0..511
            int r = lin >> 2;               // 0..127
            int c4 = (lin & 3) * 4;         // 0,4,8,12
            int row = rowBase + r;
            float4 v = make_float4(0.f, 0.f, 0.f, 0.f);
            if (row < n) v = *(const float4*)&A[(long)row * K + k0 + c4];
            As[c4 + 0][2 * r] = v.x; As[c4 + 0][2 * r + 1] = v.x;
            As[c4 + 1][2 * r] = v.y; As[c4 + 1][2 * r + 1] = v.y;
            As[c4 + 2][2 * r] = v.z; As[c4 + 2][2 * r + 1] = v.z;
            As[c4 + 3][2 * r] = v.w; As[c4 + 3][2 * r + 1] = v.w;
        }
        // load B tile (16 x 64)
        #pragma unroll
        for (int l = 0; l < 2; l++) {
            int lin = t + l * 128;          // 0..255
            int kr = lin >> 4;
            int c = (lin & 15) * 4;
            *(float4*)&Bs[kr][c] = *(const float4*)&W[(k0 + kr) * 64 + c];
        }
        __syncthreads();
        #pragma unroll
        for (int kk = 0; kk < 16; kk++) {
            unsigned long long a2[8], b2[4];
            #pragma unroll
            for (int i = 0; i < 8; i++)
                a2[i] = *(const unsigned long long*)&As[kk][(ty * 8 + i) * 2];
            #pragma unroll
            for (int q = 0; q < 4; q++)
                b2[q] = *(const unsigned long long*)&Bs[kk][tx * 8 + q * 2];
            #pragma unroll
            for (int i = 0; i < 8; i++)
                #pragma unroll
                for (int q = 0; q < 4; q++)
                    ffma2(acc[i][q], a2[i], b2[q]);
        }
        __syncthreads();
    }

    float bv[8];
    #pragma unroll
    for (int j = 0; j < 8; j++) bv[j] = bias ? bias[tx * 8 + j] : 0.f;

    #pragma unroll
    for (int i = 0; i < 8; i++) {
        int row = rowBase + ty * 8 + i;
        if (row < n) {
            float2 c0 = unpack2(acc[i][0]);
            float2 c1 = unpack2(acc[i][1]);
            float2 c2 = unpack2(acc[i][2]);
            float2 c3 = unpack2(acc[i][3]);
            float4 o0 = make_float4(c0.x + bv[0], c0.y + bv[1], c1.x + bv[2], c1.y + bv[3]);
            float4 o1 = make_float4(c2.x + bv[4], c2.y + bv[5], c3.x + bv[6], c3.y + bv[7]);
            *(float4*)&C[(long)row * 64 + tx * 8] = o0;
            *(float4*)&C[(long)row * 64 + tx * 8 + 4] = o1;
        }
    }
}

// ---------------- aggregation: warp per node, float2 per lane ----------------

__global__ void k_agg(const float* __restrict__ h, float* __restrict__ out,
                      const float* __restrict__ bias, int n, int doRelu) {
    int warp = (blockIdx.x * blockDim.x + threadIdx.x) >> 5;
    int lane = threadIdx.x & 31;
    if (warp >= n) return;
    int start = g_rowptr[warp];
    int cnt = g_cnt[warp];
    const float2* hp = (const float2*)h;
    float ax = 0.f, ay = 0.f;
    for (int i = 0; i < cnt; i++) {
        int s = __ldg(&g_ssrc[start + i]);
        float nrm = __ldg(&g_snorm[start + i]);
        float2 v = hp[(long)s * 32 + lane];
        ax += v.x * nrm;
        ay += v.y * nrm;
    }
    // self loop
    float di = g_dinv[warp];
    float sn = di * di;
    float2 sv = hp[(long)warp * 32 + lane];
    ax += sv.x * sn;
    ay += sv.y * sn;
    // bias (+ optional relu)
    ax += bias[lane * 2];
    ay += bias[lane * 2 + 1];
    if (doRelu) { ax = fmaxf(ax, 0.f); ay = fmaxf(ay, 0.f); }
    float2 o; o.x = ax; o.y = ay;
    ((float2*)out)[(long)warp * 32 + lane] = o;
}

// ---------------- launcher ----------------

extern "C" void kernel_launch(void* const* d_in, const int* in_sizes, int n_in,
                              void* d_out, int out_size) {
    const float* x  = (const float*)d_in[0];
    const int*   ei = (const int*)d_in[1];
    const float* w  = (const float*)d_in[2];
    const float* Wm = (const float*)d_in[3];
    const float* bm = (const float*)d_in[4];
    const float* W1 = (const float*)d_in[5];
    const float* b1 = (const float*)d_in[6];
    const float* W2 = (const float*)d_in[7];
    const float* b2 = (const float*)d_in[8];

    int e = in_sizes[2];
    int n = in_sizes[0] / 384;
    const int* src = ei;
    const int* dst = ei + e;

    void *p_h, *p_agg, *p_Wf, *p_bf;
    cudaGetSymbolAddress(&p_h,   g_h);
    cudaGetSymbolAddress(&p_agg, g_agg);
    cudaGetSymbolAddress(&p_Wf,  g_Wf);
    cudaGetSymbolAddress(&p_bf,  g_bf);
    float* h   = (float*)p_h;
    float* agg = (float*)p_agg;
    float* Wf  = (float*)p_Wf;
    float* bf  = (float*)p_bf;

    int nb = (n + 1023) / 1024;

    // fused layer-1 weights (independent of graph preprocessing)
    k_fuseW<<<(384 * 64 + 255) / 256, 256>>>(Wm, W1, Wf);
    k_fuseb<<<1, 64>>>(bm, W1, bf);

    // graph preprocessing (CSR + norms), reused by both layers
    k_init<<<(n + 255) / 256, 256>>>(n);
    k_deg<<<(e + 255) / 256, 256>>>(src, dst, w, e);
    k_dinv<<<(n + 255) / 256, 256>>>(n);
    k_scan1<<<nb, 1024>>>(n);
    k_scan2<<<1, 128>>>(nb);
    k_scan3<<<(n + 255) / 256, 256>>>(n);
    k_fill<<<(e + 255) / 256, 256>>>(src, dst, w, e);

    // layer 1 (fused): h = x @ Wf + bf ; agg = relu(aggregate(h) + b1)
    k_gemm<<<(n + 127) / 128, 128>>>(x, Wf, bf, h, n, 384);
    k_agg<<<(n + 7) / 8, 256>>>(h, agg, b1, n, 1);

    // layer 2: h = agg @ W2 ; out = aggregate(h) + b2
    k_gemm<<<(n + 127) / 128, 128>>>(agg, W2, nullptr, h, n, 64);
    k_agg<<<(n + 7) / 8, 256>>>(h, (float*)d_out, b2, n, 0);
}

// round 3
// speedup vs baseline: 1.2493x; 1.2493x over previous
#include <cuda_runtime.h>

#define NMAX 100000
#define EMAX 800000

// Scratch (static __device__ arrays per allocation rules)
__device__ float g_h[NMAX * 64];     // per-layer transformed features
__device__ float g_agg[NMAX * 64];   // layer-1 output (post relu)
__device__ float g_Wf[384 * 64];     // Wm @ W1 fused weight
__device__ float g_bf[64];           // bm @ W1 fused bias
__device__ float g_dinv[NMAX];       // deg accumulator, then rsqrt(deg)
__device__ int   g_cnt[NMAX];        // in-degree (edge count) per node
__device__ int   g_rowptr[NMAX];     // exclusive prefix of g_cnt
__device__ int   g_pos[NMAX];        // fill cursors
__device__ int   g_ssrc[EMAX];       // CSR: source node per (dst-sorted) edge
__device__ float g_snorm[EMAX];      // CSR: norm per (dst-sorted) edge
__device__ int   g_bsum[128];
__device__ int   g_bscan[128];

// ---------------- preprocessing ----------------

__global__ void k_init(int n) {
    int i = blockIdx.x * blockDim.x + threadIdx.x;
    if (i < n) { g_dinv[i] = 1.0f; g_cnt[i] = 0; }  // self-loop weight 1 pre-seeded
}

__global__ void k_deg(const int* __restrict__ src, const int* __restrict__ dst,
                      const float* __restrict__ w, int e) {
    int i = blockIdx.x * blockDim.x + threadIdx.x;
    if (i < e) {
        int d = dst[i];
        atomicAdd(&g_dinv[d], w[i]);
        atomicAdd(&g_cnt[d], 1);
    }
}

__global__ void k_dinv(int n) {
    int i = blockIdx.x * blockDim.x + threadIdx.x;
    if (i < n) g_dinv[i] = rsqrtf(g_dinv[i]);   // deg >= 1 always (self loop)
}

__global__ void k_scan1(int n) {   // 1024 threads/block
    __shared__ int sh[1024];
    int t = threadIdx.x;
    int i = blockIdx.x * 1024 + t;
    int v = (i < n) ? g_cnt[i] : 0;
    sh[t] = v; __syncthreads();
    #pragma unroll
    for (int off = 1; off < 1024; off <<= 1) {
        int x = (t >= off) ? sh[t - off] : 0;
        __syncthreads();
        sh[t] += x;
        __syncthreads();
    }
    if (i < n) g_rowptr[i] = sh[t] - v;          // block-local exclusive
    if (t == 1023) g_bsum[blockIdx.x] = sh[1023];
}

__global__ void k_scan2(int nb) {  // single block of 128
    __shared__ int sh[128];
    int t = threadIdx.x;
    int v = (t < nb) ? g_bsum[t] : 0;
    sh[t] = v; __syncthreads();
    #pragma unroll
    for (int off = 1; off < 128; off <<= 1) {
        int x = (t >= off) ? sh[t - off] : 0;
        __syncthreads();
        sh[t] += x;
        __syncthreads();
    }
    if (t < nb) g_bscan[t] = sh[t] - v;
}

__global__ void k_scan3(int n) {
    int i = blockIdx.x * blockDim.x + threadIdx.x;
    if (i < n) {
        int r = g_rowptr[i] + g_bscan[i >> 10];
        g_rowptr[i] = r;
        g_pos[i] = r;
    }
}

__global__ void k_fill(const int* __restrict__ src, const int* __restrict__ dst,
                       const float* __restrict__ w, int e) {
    int i = blockIdx.x * blockDim.x + threadIdx.x;
    if (i < e) {
        int d = dst[i], s = src[i];
        int p = atomicAdd(&g_pos[d], 1);
        g_ssrc[p] = s;
        g_snorm[p] = g_dinv[s] * w[i] * g_dinv[d];
    }
}

// ---------------- weight fusion: Wf = Wm @ W1, bf = bm @ W1 ----------------

__global__ void k_fuseW(const float* __restrict__ Wm, const float* __restrict__ W1,
                        float* __restrict__ Wf) {
    int i = blockIdx.x * blockDim.x + threadIdx.x;   // 0..384*64
    if (i >= 384 * 64) return;
    int r = i >> 6, c = i & 63;
    float s = 0.f;
    #pragma unroll 8
    for (int k = 0; k < 64; k++) s += Wm[r * 64 + k] * W1[k * 64 + c];
    Wf[i] = s;
}

__global__ void k_fuseb(const float* __restrict__ bm, const float* __restrict__ W1,
                        float* __restrict__ bf) {
    int c = threadIdx.x;
    float s = 0.f;
    #pragma unroll 8
    for (int k = 0; k < 64; k++) s += bm[k] * W1[k * 64 + c];
    bf[c] = s;
}

// ---------------- FFMA2 GEMM: C[n,64] = A[n,K] @ W[K,64] (+bias) ----------
// BM=128, BN=64, BK=16, 256 threads (8 warps).
// Per-thread: 8 rows (as 4 packed row-pairs) x 4 cols.
// Row-pairs come free as contiguous LDS.64 from transposed As (broadcast,
// conflict-free); B loads as one LDS.128 then packs (b,b) via ALU-pipe MOVs.
// acc.{x,y} = rows {2i, 2i+1}: exact fp32 semantics, just SIMD-2.

__device__ __forceinline__ void ffma2(unsigned long long& d,
                                      unsigned long long a,
                                      unsigned long long b) {
    asm volatile("fma.rn.f32x2 %0, %1, %2, %0;" : "+l"(d) : "l"(a), "l"(b));
}

__device__ __forceinline__ unsigned long long pack2(float v) {
    unsigned long long r;
    asm("mov.b64 %0, {%1, %1};" : "=l"(r) : "f"(v));
    return r;
}

__device__ __forceinline__ float2 unpack2(unsigned long long v) {
    float2 r;
    asm("mov.b64 {%0, %1}, %2;" : "=f"(r.x), "=f"(r.y) : "l"(v));
    return r;
}

__global__ __launch_bounds__(256)
void k_gemm(const float* __restrict__ A, const float* __restrict__ W,
            const float* __restrict__ bias, float* __restrict__ C,
            int n, int K) {
    __shared__ float As[16][132];   // transposed A tile, padded: store bank = r + 4c (conflict-free)
    __shared__ float Bs[16][64];
    int t = threadIdx.x;
    int rowBase = blockIdx.x * 128;
    int ty = t >> 4;          // 0..15 -> 8 rows each (4 row-pairs)
    int tx = t & 15;          // 0..15 -> 4 cols each

    unsigned long long acc[4][4];   // [row-pair][col]
    #pragma unroll
    for (int i = 0; i < 4; i++)
        #pragma unroll
        for (int j = 0; j < 4; j++) acc[i][j] = 0ull;

    for (int k0 = 0; k0 < K; k0 += 16) {
        // load A tile (128 rows x 16 k), transposed into As[k][row]
        #pragma unroll
        for (int l = 0; l < 2; l++) {
            int lin = t + l * 256;          // 0..511
            int r = lin >> 2;               // 0..127
            int c4 = (lin & 3) * 4;         // 0,4,8,12
            int row = rowBase + r;
            float4 v = make_float4(0.f, 0.f, 0.f, 0.f);
            if (row < n) v = *(const float4*)&A[(long)row * K + k0 + c4];
            As[c4 + 0][r] = v.x;
            As[c4 + 1][r] = v.y;
            As[c4 + 2][r] = v.z;
            As[c4 + 3][r] = v.w;
        }
        // load B tile (16 x 64): one float4 per thread
        {
            int kr = t >> 4;
            int c = (t & 15) * 4;
            *(float4*)&Bs[kr][c] = *(const float4*)&W[(k0 + kr) * 64 + c];
        }
        __syncthreads();
        #pragma unroll
        for (int kk = 0; kk < 16; kk++) {
            unsigned long long a2[4];
            #pragma unroll
            for (int i = 0; i < 4; i++)
                a2[i] = *(const unsigned long long*)&As[kk][ty * 8 + 2 * i];
            float4 b4 = *(const float4*)&Bs[kk][tx * 4];
            unsigned long long bb[4];
            bb[0] = pack2(b4.x); bb[1] = pack2(b4.y);
            bb[2] = pack2(b4.z); bb[3] = pack2(b4.w);
            #pragma unroll
            for (int i = 0; i < 4; i++)
                #pragma unroll
                for (int j = 0; j < 4; j++)
                    ffma2(acc[i][j], a2[i], bb[j]);
        }
        __syncthreads();
    }

    float bv[4];
    #pragma unroll
    for (int j = 0; j < 4; j++) bv[j] = bias ? bias[tx * 4 + j] : 0.f;

    #pragma unroll
    for (int i = 0; i < 4; i++) {
        int row0 = rowBase + ty * 8 + 2 * i;
        float2 c0 = unpack2(acc[i][0]);
        float2 c1 = unpack2(acc[i][1]);
        float2 c2 = unpack2(acc[i][2]);
        float2 c3 = unpack2(acc[i][3]);
        if (row0 < n) {
            float4 o = make_float4(c0.x + bv[0], c1.x + bv[1], c2.x + bv[2], c3.x + bv[3]);
            *(float4*)&C[(long)row0 * 64 + tx * 4] = o;
        }
        if (row0 + 1 < n) {
            float4 o = make_float4(c0.y + bv[0], c1.y + bv[1], c2.y + bv[2], c3.y + bv[3]);
            *(float4*)&C[(long)(row0 + 1) * 64 + tx * 4] = o;
        }
    }
}

// ---------------- aggregation: warp per node, float2 per lane ----------------

__global__ void k_agg(const float* __restrict__ h, float* __restrict__ out,
                      const float* __restrict__ bias, int n, int doRelu) {
    int warp = (blockIdx.x * blockDim.x + threadIdx.x) >> 5;
    int lane = threadIdx.x & 31;
    if (warp >= n) return;
    int start = g_rowptr[warp];
    int cnt = g_cnt[warp];
    const float2* hp = (const float2*)h;
    float ax = 0.f, ay = 0.f;
    for (int i = 0; i < cnt; i++) {
        int s = __ldg(&g_ssrc[start + i]);
        float nrm = __ldg(&g_snorm[start + i]);
        float2 v = hp[(long)s * 32 + lane];
        ax += v.x * nrm;
        ay += v.y * nrm;
    }
    // self loop
    float di = g_dinv[warp];
    float sn = di * di;
    float2 sv = hp[(long)warp * 32 + lane];
    ax += sv.x * sn;
    ay += sv.y * sn;
    // bias (+ optional relu)
    ax += bias[lane * 2];
    ay += bias[lane * 2 + 1];
    if (doRelu) { ax = fmaxf(ax, 0.f); ay = fmaxf(ay, 0.f); }
    float2 o; o.x = ax; o.y = ay;
    ((float2*)out)[(long)warp * 32 + lane] = o;
}

// ---------------- launcher ----------------

extern "C" void kernel_launch(void* const* d_in, const int* in_sizes, int n_in,
                              void* d_out, int out_size) {
    const float* x  = (const float*)d_in[0];
    const int*   ei = (const int*)d_in[1];
    const float* w  = (const float*)d_in[2];
    const float* Wm = (const float*)d_in[3];
    const float* bm = (const float*)d_in[4];
    const float* W1 = (const float*)d_in[5];
    const float* b1 = (const float*)d_in[6];
    const float* W2 = (const float*)d_in[7];
    const float* b2 = (const float*)d_in[8];

    int e = in_sizes[2];
    int n = in_sizes[0] / 384;
    const int* src = ei;
    const int* dst = ei + e;

    void *p_h, *p_agg, *p_Wf, *p_bf;
    cudaGetSymbolAddress(&p_h,   g_h);
    cudaGetSymbolAddress(&p_agg, g_agg);
    cudaGetSymbolAddress(&p_Wf,  g_Wf);
    cudaGetSymbolAddress(&p_bf,  g_bf);
    float* h   = (float*)p_h;
    float* agg = (float*)p_agg;
    float* Wf  = (float*)p_Wf;
    float* bf  = (float*)p_bf;

    int nb = (n + 1023) / 1024;

    // fused layer-1 weights (independent of graph preprocessing)
    k_fuseW<<<(384 * 64 + 255) / 256, 256>>>(Wm, W1, Wf);
    k_fuseb<<<1, 64>>>(bm, W1, bf);

    // graph preprocessing (CSR + norms), reused by both layers
    k_init<<<(n + 255) / 256, 256>>>(n);
    k_deg<<<(e + 255) / 256, 256>>>(src, dst, w, e);
    k_dinv<<<(n + 255) / 256, 256>>>(n);
    k_scan1<<<nb, 1024>>>(n);
    k_scan2<<<1, 128>>>(nb);
    k_scan3<<<(n + 255) / 256, 256>>>(n);
    k_fill<<<(e + 255) / 256, 256>>>(src, dst, w, e);

    // layer 1 (fused): h = x @ Wf + bf ; agg = relu(aggregate(h) + b1)
    k_gemm<<<(n + 127) / 128, 256>>>(x, Wf, bf, h, n, 384);
    k_agg<<<(n + 7) / 8, 256>>>(h, agg, b1, n, 1);

    // layer 2: h = agg @ W2 ; out = aggregate(h) + b2
    k_gemm<<<(n + 127) / 128, 256>>>(agg, W2, nullptr, h, n, 64);
    k_agg<<<(n + 7) / 8, 256>>>(h, (float*)d_out, b2, n, 0);
}